// round 16
// baseline (speedup 1.0000x reference)
#include <cuda_runtime.h>

#define Bc 128
#define Nc 256
#define Mc 1024
#define M4 (Mc/4)          // 256 float4 per row
#define BSTRIDE4 (Nc*M4)   // float4 per batch
#define NSPLIT 8
#define NCHUNK (Nc/NSPLIT) // 32 rows per split

// Scratch (allocation-free per harness rules)
__device__ float g_dot[Bc*Nc];
__device__ float g_msq[Bc*Nc];

// ---------------------------------------------------------------------------
// Kernel 1: per-(b,n) dot(memory_row, k) and ||memory_row||^2.
// Block = (b, 64-row chunk); warp caches its k slice in 32 regs ONCE, then
// streams 8 rows with memory-only LDG.128 (halved LDG count, k L1 traffic
// eliminated). First 128 blocks also zero the read accumulator.
// ---------------------------------------------------------------------------
__global__ void __launch_bounds__(256, 3)
sim_kernel(const float4* __restrict__ mem,
           const float4* __restrict__ k,
           float4* __restrict__ read_out) {
    if (blockIdx.x < Bc) {
        read_out[blockIdx.x * M4 + threadIdx.x] = make_float4(0.f, 0.f, 0.f, 0.f);
    }

    int warp  = threadIdx.x >> 5;
    int lane  = threadIdx.x & 31;
    int b     = blockIdx.x >> 2;           // 4 chunks per batch
    int chunk = blockIdx.x & 3;

    // Cache this lane's k slice: 8 float4, loaded once per warp.
    const float4* kr = k + b * M4;
    float4 kq[8];
#pragma unroll
    for (int j = 0; j < 8; j++) kq[j] = kr[lane + j * 32];

    int row0 = b * Nc + chunk * 64 + warp * 8;     // 8 rows per warp
    const float4* mr = mem + (size_t)row0 * M4;

#pragma unroll 2
    for (int r = 0; r < 8; r++) {
        float dot = 0.f, msq = 0.f;
#pragma unroll
        for (int j = 0; j < 8; j++) {
            float4 m4 = mr[r * M4 + lane + j * 32];
            dot += m4.x * kq[j].x + m4.y * kq[j].y + m4.z * kq[j].z + m4.w * kq[j].w;
            msq += m4.x * m4.x + m4.y * m4.y + m4.z * m4.z + m4.w * m4.w;
        }
#pragma unroll
        for (int o = 16; o > 0; o >>= 1) {
            dot += __shfl_xor_sync(0xFFFFFFFFu, dot, o);
            msq += __shfl_xor_sync(0xFFFFFFFFu, msq, o);
        }
        if (lane == 0) {
            g_dot[row0 + r] = dot;
            g_msq[row0 + r] = msq;
        }
    }
}

// ---------------------------------------------------------------------------
// Block reductions (256 threads = 8 warps)
// ---------------------------------------------------------------------------
__device__ __forceinline__ float block_reduce_sum(float v, float* sm) {
#pragma unroll
    for (int o = 16; o > 0; o >>= 1) v += __shfl_xor_sync(0xFFFFFFFFu, v, o);
    int warp = threadIdx.x >> 5, lane = threadIdx.x & 31;
    if (lane == 0) sm[warp] = v;
    __syncthreads();
    if (warp == 0) {
        v = (lane < 8) ? sm[lane] : 0.f;
#pragma unroll
        for (int o = 4; o > 0; o >>= 1) v += __shfl_xor_sync(0xFFFFFFFFu, v, o);
        if (lane == 0) sm[0] = v;
    }
    __syncthreads();
    v = sm[0];
    __syncthreads();
    return v;
}

__device__ __forceinline__ float block_reduce_max(float v, float* sm) {
#pragma unroll
    for (int o = 16; o > 0; o >>= 1) v = fmaxf(v, __shfl_xor_sync(0xFFFFFFFFu, v, o));
    int warp = threadIdx.x >> 5, lane = threadIdx.x & 31;
    if (lane == 0) sm[warp] = v;
    __syncthreads();
    if (warp == 0) {
        v = (lane < 8) ? sm[lane] : -3.4e38f;
#pragma unroll
        for (int o = 4; o > 0; o >>= 1) v = fmaxf(v, __shfl_xor_sync(0xFFFFFFFFu, v, o));
        if (lane == 0) sm[0] = v;
    }
    __syncthreads();
    v = sm[0];
    __syncthreads();
    return v;
}

// ---------------------------------------------------------------------------
// Kernel 2 (fused): weight pipeline preamble + erase/add write + atomic read
// fold. Grid (NSPLIT, B), 256 threads.
// Cache policy: memory read = __ldlu (last-use), newmem store = __stcs
// (evict-first) — preserves the L2 footprint sim_kernel left behind.
// ---------------------------------------------------------------------------
__global__ void write_kernel(const float4* __restrict__ mem,
                             const float4* __restrict__ e,
                             const float4* __restrict__ a,
                             const float*  __restrict__ k,
                             const float*  __restrict__ beta,
                             const float*  __restrict__ g,
                             const float*  __restrict__ s,
                             const float*  __restrict__ gamma,
                             const float*  __restrict__ w_prev,
                             float* __restrict__ w_out,
                             float4* __restrict__ newmem,
                             float* __restrict__ read_out) {
    __shared__ float sred[32];
    __shared__ float sw[Nc];

    int sp = blockIdx.x;                 // 0..NSPLIT-1
    int b  = (Bc - 1) - blockIdx.y;      // reversed batch order (L2 tail reuse)
    int t  = threadIdx.x;                // 0..255 (also n index for weights)
    int nbase = sp * NCHUNK;

    // Issue the streaming operand loads early (overlap with weight preamble)
    float4 e4 = e[b * M4 + t];
    float4 a4 = a[b * M4 + t];

    // ---- weight pipeline (redundant across sp; deterministic) ----
    const float* kb = k + b * Mc;
    float kq = 0.f;
#pragma unroll
    for (int j = 0; j < 4; j++) {
        float v = kb[t + j * 256];
        kq += v * v;
    }
    kq = block_reduce_sum(kq, sred);
    float knorm = fmaxf(sqrtf(kq), 1e-8f);

    float mnorm = fmaxf(sqrtf(g_msq[b * Nc + t]), 1e-8f);
    float cosv  = g_dot[b * Nc + t] / (mnorm * knorm);

    float x    = beta[b] * cosv;
    float xmax = block_reduce_max(x, sred);
    float p    = expf(x - xmax);
    float psum = block_reduce_sum(p, sred);
    float wc   = p / psum;

    float gg = g[b];
    float wg = gg * wc + (1.f - gg) * w_prev[b * Nc + t];
    sw[t] = wg;
    __syncthreads();

    float s0 = s[b * 3 + 0], s1 = s[b * 3 + 1], s2 = s[b * 3 + 2];
    float wt = s0 * sw[(t + Nc - 1) & (Nc - 1)]
             + s1 * sw[t]
             + s2 * sw[(t + 1) & (Nc - 1)];

    float wp   = powf(wt, gamma[b]);
    float wsum = block_reduce_sum(wp, sred);
    float wfin = wp / (wsum + 1e-16f);

    if (sp == 0) w_out[b * Nc + t] = wfin;   // emit w output once per b

    __syncthreads();          // all taps/reduce reads of sw done
    sw[t] = wfin;
    __syncthreads();

    // ---- streaming erase/add + read fold ----
    const float4* mb = mem    + (size_t)b * BSTRIDE4 + (size_t)nbase * M4 + t;
    float4*       nb = newmem + (size_t)b * BSTRIDE4 + (size_t)nbase * M4 + t;

    float4 acc = make_float4(0.f, 0.f, 0.f, 0.f);

#pragma unroll 2
    for (int n0 = NCHUNK - 4; n0 >= 0; n0 -= 4) {
        float4 v0 = __ldlu(&mb[(n0 + 3) * M4]);
        float4 v1 = __ldlu(&mb[(n0 + 2) * M4]);
        float4 v2 = __ldlu(&mb[(n0 + 1) * M4]);
        float4 v3 = __ldlu(&mb[(n0 + 0) * M4]);
        float w0 = sw[nbase + n0 + 3], w1 = sw[nbase + n0 + 2];
        float w2 = sw[nbase + n0 + 1], w3 = sw[nbase + n0 + 0];

        float4 r;
        r.x = v0.x * (1.f - w0 * e4.x) + w0 * a4.x;
        r.y = v0.y * (1.f - w0 * e4.y) + w0 * a4.y;
        r.z = v0.z * (1.f - w0 * e4.z) + w0 * a4.z;
        r.w = v0.w * (1.f - w0 * e4.w) + w0 * a4.w;
        __stcs(&nb[(n0 + 3) * M4], r);
        acc.x += w0 * r.x; acc.y += w0 * r.y; acc.z += w0 * r.z; acc.w += w0 * r.w;

        r.x = v1.x * (1.f - w1 * e4.x) + w1 * a4.x;
        r.y = v1.y * (1.f - w1 * e4.y) + w1 * a4.y;
        r.z = v1.z * (1.f - w1 * e4.z) + w1 * a4.z;
        r.w = v1.w * (1.f - w1 * e4.w) + w1 * a4.w;
        __stcs(&nb[(n0 + 2) * M4], r);
        acc.x += w1 * r.x; acc.y += w1 * r.y; acc.z += w1 * r.z; acc.w += w1 * r.w;

        r.x = v2.x * (1.f - w2 * e4.x) + w2 * a4.x;
        r.y = v2.y * (1.f - w2 * e4.y) + w2 * a4.y;
        r.z = v2.z * (1.f - w2 * e4.z) + w2 * a4.z;
        r.w = v2.w * (1.f - w2 * e4.w) + w2 * a4.w;
        __stcs(&nb[(n0 + 1) * M4], r);
        acc.x += w2 * r.x; acc.y += w2 * r.y; acc.z += w2 * r.z; acc.w += w2 * r.w;

        r.x = v3.x * (1.f - w3 * e4.x) + w3 * a4.x;
        r.y = v3.y * (1.f - w3 * e4.y) + w3 * a4.y;
        r.z = v3.z * (1.f - w3 * e4.z) + w3 * a4.z;
        r.w = v3.w * (1.f - w3 * e4.w) + w3 * a4.w;
        __stcs(&nb[(n0 + 0) * M4], r);
        acc.x += w3 * r.x; acc.y += w3 * r.y; acc.z += w3 * r.z; acc.w += w3 * r.w;
    }

    float* ro = read_out + b * Mc + t * 4;
    atomicAdd(ro + 0, acc.x);
    atomicAdd(ro + 1, acc.y);
    atomicAdd(ro + 2, acc.z);
    atomicAdd(ro + 3, acc.w);
}

// ---------------------------------------------------------------------------
// Launch
// ---------------------------------------------------------------------------
extern "C" void kernel_launch(void* const* d_in, const int* in_sizes, int n_in,
                              void* d_out, int out_size) {
    const float* memory = (const float*)d_in[0];   // (B, N, M)
    const float* k      = (const float*)d_in[1];   // (B, M)
    const float* beta   = (const float*)d_in[2];   // (B, 1)
    const float* g      = (const float*)d_in[3];   // (B, 1)
    const float* s      = (const float*)d_in[4];   // (B, 3)
    const float* gamma  = (const float*)d_in[5];   // (B, 1)
    const float* w_prev = (const float*)d_in[6];   // (B, N)
    const float* e      = (const float*)d_in[7];   // (B, M)
    const float* a      = (const float*)d_in[8];   // (B, M)

    float* out      = (float*)d_out;
    float* out_read = out;                             // (B, M)
    float* out_mem  = out + Bc * Mc;                   // (B, N, M)
    float* out_w    = out + Bc * Mc + (size_t)Bc * Nc * Mc;  // (B, N)

    // Pass A: dots + norms + read_out zero-init (k register-cached)
    sim_kernel<<<Bc * 4, 256>>>((const float4*)memory, (const float4*)k,
                                (float4*)out_read);

    // Pass B (fused): weights + erase/add + read fold (cache-controlled)
    dim3 grid2(NSPLIT, Bc);
    write_kernel<<<grid2, 256>>>((const float4*)memory, (const float4*)e,
                                 (const float4*)a, k, beta, g, s, gamma,
                                 w_prev, out_w, (float4*)out_mem, out_read);
}